// round 1
// baseline (speedup 1.0000x reference)
#include <cuda_runtime.h>

// ---------------- problem constants ----------------
// N=8, S=384, E=768, H=12, D=64, P=384, 2P=768
// out = concat(out[8,384,768], attn[8,12,384,384]) as fp32

#define NEG_INF __int_as_float(0xff800000)

static __device__ float g_qh [8*384*768];      // 9.4 MB
static __device__ float g_kc [8*384*768];
static __device__ float g_v  [8*384*768];
static __device__ float g_kpe[768*768];        // 2.4 MB
static __device__ float g_z  [28311552];       // 8*12*384*768 = 113 MB
static __device__ float g_oh [8*384*768];
static __device__ float g_attn_fb[14155776];   // fallback if out_size excludes attn

// ================= generic  C = A @ W^T + bias =================
// A: [M,K] row-major, W: [N,K] row-major, C: [M,N]. M,N mult of 64, K mult of 16.
__global__ void __launch_bounds__(256) gemm_nt_bias_kernel(
    const float* __restrict__ A, const float* __restrict__ W,
    const float* __restrict__ bias, float* __restrict__ C,
    int M, int N, int K)
{
    __shared__ float As[16][68];
    __shared__ float Bs[16][68];
    const int tid = threadIdx.x;
    const int tx = tid & 15, ty = tid >> 4;
    const int m0 = blockIdx.y * 64, n0 = blockIdx.x * 64;
    const int lr = tid >> 2;            // 0..63
    const int lk = (tid & 3) << 2;      // 0,4,8,12
    float acc[4][4] = {};
    for (int k0 = 0; k0 < K; k0 += 16) {
        float4 a = *(const float4*)(A + (size_t)(m0 + lr) * K + k0 + lk);
        float4 b = *(const float4*)(W + (size_t)(n0 + lr) * K + k0 + lk);
        As[lk+0][lr]=a.x; As[lk+1][lr]=a.y; As[lk+2][lr]=a.z; As[lk+3][lr]=a.w;
        Bs[lk+0][lr]=b.x; Bs[lk+1][lr]=b.y; Bs[lk+2][lr]=b.z; Bs[lk+3][lr]=b.w;
        __syncthreads();
        #pragma unroll
        for (int kk = 0; kk < 16; kk++) {
            float4 av = *(const float4*)&As[kk][ty*4];
            float4 bv = *(const float4*)&Bs[kk][tx*4];
            float qa[4] = {av.x, av.y, av.z, av.w};
            float kb[4] = {bv.x, bv.y, bv.z, bv.w};
            #pragma unroll
            for (int i = 0; i < 4; i++)
                #pragma unroll
                for (int j = 0; j < 4; j++)
                    acc[i][j] = fmaf(qa[i], kb[j], acc[i][j]);
        }
        __syncthreads();
    }
    #pragma unroll
    for (int i = 0; i < 4; i++) {
        float4 o;
        o.x = acc[i][0] + bias[n0 + tx*4 + 0];
        o.y = acc[i][1] + bias[n0 + tx*4 + 1];
        o.z = acc[i][2] + bias[n0 + tx*4 + 2];
        o.w = acc[i][3] + bias[n0 + tx*4 + 3];
        *(float4*)(C + (size_t)(m0 + ty*4 + i) * N + n0 + tx*4) = o;
    }
}

// ================= Z[b,q,c] = sum_d qh[n,q,h*64+d] * kpe[c,h*64+d] =================
// b = n*12+h ; grid (12 c-tiles, 6 q-tiles, 96 batches)
__global__ void __launch_bounds__(256) zgemm_kernel(
    const float* __restrict__ qh, const float* __restrict__ kpe, float* __restrict__ z)
{
    const int b = blockIdx.z, n = b / 12, h = b % 12;
    const int q0 = blockIdx.y * 64, c0 = blockIdx.x * 64;
    const int tid = threadIdx.x;
    const int tx = tid & 15, ty = tid >> 4;
    const int lr = tid >> 2, lk = (tid & 3) << 2;
    __shared__ float As[16][68];
    __shared__ float Bs[16][68];
    const float* A = qh  + (size_t)(n * 384) * 768 + h * 64;
    const float* B = kpe + h * 64;
    float acc[4][4] = {};
    #pragma unroll
    for (int k0 = 0; k0 < 64; k0 += 16) {
        float4 a  = *(const float4*)(A + (size_t)(q0 + lr) * 768 + k0 + lk);
        float4 bb = *(const float4*)(B + (size_t)(c0 + lr) * 768 + k0 + lk);
        As[lk+0][lr]=a.x;  As[lk+1][lr]=a.y;  As[lk+2][lr]=a.z;  As[lk+3][lr]=a.w;
        Bs[lk+0][lr]=bb.x; Bs[lk+1][lr]=bb.y; Bs[lk+2][lr]=bb.z; Bs[lk+3][lr]=bb.w;
        __syncthreads();
        #pragma unroll
        for (int kk = 0; kk < 16; kk++) {
            float4 av = *(const float4*)&As[kk][ty*4];
            float4 bv = *(const float4*)&Bs[kk][tx*4];
            float qa[4] = {av.x, av.y, av.z, av.w};
            float kb[4] = {bv.x, bv.y, bv.z, bv.w};
            #pragma unroll
            for (int i = 0; i < 4; i++)
                #pragma unroll
                for (int j = 0; j < 4; j++)
                    acc[i][j] = fmaf(qa[i], kb[j], acc[i][j]);
        }
        __syncthreads();
    }
    float* Cc = z + (size_t)b * 384 * 768;
    #pragma unroll
    for (int i = 0; i < 4; i++) {
        float4 o = {acc[i][0], acc[i][1], acc[i][2], acc[i][3]};
        *(float4*)(Cc + (size_t)(q0 + ty*4 + i) * 768 + c0 + tx*4) = o;
    }
}

// ================= scores (= qh·kc^T + Z gather), mask, softmax -> attn =================
// grid (6 q-tiles, 12 h, 8 n); block 256 (tx=k-lane 0..15, ty=q-group 0..15)
__global__ void __launch_bounds__(256) scores_softmax_kernel(
    const float* __restrict__ qh, const float* __restrict__ kc,
    const float* __restrict__ z,  const int* __restrict__ mask,
    float* __restrict__ attn)
{
    const int n = blockIdx.z, h = blockIdx.y, q0 = blockIdx.x * 64;
    const int tid = threadIdx.x;
    const int tx = tid & 15, ty = tid >> 4;

    __shared__ float Qs[64][68];   // Qs[d][qi]
    __shared__ float Ks[64][68];   // Ks[d][kj]

    // load Q tile (64 q x 64 d), transposed into smem
    {
        const float* Aq = qh + (size_t)(n * 384 + q0) * 768 + h * 64;
        const int c4 = (tid & 15) * 4;
        const int r0 = tid >> 4;
        #pragma unroll
        for (int t = 0; t < 4; t++) {
            int row = r0 + t * 16;
            float4 a = *(const float4*)(Aq + (size_t)row * 768 + c4);
            Qs[c4+0][row] = a.x; Qs[c4+1][row] = a.y;
            Qs[c4+2][row] = a.z; Qs[c4+3][row] = a.w;
        }
    }

    float acc[6][4][4];
    #pragma unroll
    for (int kt = 0; kt < 6; kt++)
        #pragma unroll
        for (int i = 0; i < 4; i++)
            #pragma unroll
            for (int j = 0; j < 4; j++) acc[kt][i][j] = 0.f;

    const float* Bk = kc + (size_t)(n * 384) * 768 + h * 64;

    #pragma unroll
    for (int kt = 0; kt < 6; kt++) {
        __syncthreads();   // previous tile's compute done before overwrite
        {
            const int c4 = (tid & 15) * 4;
            const int r0 = tid >> 4;
            #pragma unroll
            for (int t = 0; t < 4; t++) {
                int row = r0 + t * 16;
                float4 a = *(const float4*)(Bk + (size_t)(kt*64 + row) * 768 + c4);
                Ks[c4+0][row] = a.x; Ks[c4+1][row] = a.y;
                Ks[c4+2][row] = a.z; Ks[c4+3][row] = a.w;
            }
        }
        __syncthreads();
        #pragma unroll 4
        for (int d = 0; d < 64; d++) {
            float4 qv = *(const float4*)&Qs[d][ty*4];
            float4 kv = *(const float4*)&Ks[d][tx*4];
            float qa[4] = {qv.x, qv.y, qv.z, qv.w};
            float kb[4] = {kv.x, kv.y, kv.z, kv.w};
            #pragma unroll
            for (int i = 0; i < 4; i++)
                #pragma unroll
                for (int j = 0; j < 4; j++)
                    acc[kt][i][j] = fmaf(qa[i], kb[j], acc[kt][i][j]);
        }
    }

    // epilogue: add relative-position term, scale, mask, softmax
    const float inv_tau = 0.036084391824351615f;  // 1/sqrt(768)
    const size_t zbase = (size_t)(n * 12 + h) * 384 * 768;
    const int* mrow = mask + n * 384;

    #pragma unroll
    for (int i = 0; i < 4; i++) {
        const int q = q0 + ty*4 + i;
        const float* zrow = z + zbase + (size_t)q * 768 + (384 - q);  // + k gives c=k-q+384
        #pragma unroll
        for (int kt = 0; kt < 6; kt++)
            #pragma unroll
            for (int j = 0; j < 4; j++) {
                const int k = kt*64 + tx*4 + j;
                float s = (acc[kt][i][j] + zrow[k]) * inv_tau;
                if (mrow[k] == 0) s = NEG_INF;
                acc[kt][i][j] = s;
            }
    }

    float rinv[4];
    #pragma unroll
    for (int i = 0; i < 4; i++) {
        float m = NEG_INF;
        #pragma unroll
        for (int kt = 0; kt < 6; kt++)
            #pragma unroll
            for (int j = 0; j < 4; j++) m = fmaxf(m, acc[kt][i][j]);
        #pragma unroll
        for (int o = 8; o >= 1; o >>= 1)
            m = fmaxf(m, __shfl_xor_sync(0xffffffffu, m, o));
        float s = 0.f;
        #pragma unroll
        for (int kt = 0; kt < 6; kt++)
            #pragma unroll
            for (int j = 0; j < 4; j++) {
                float p = __expf(acc[kt][i][j] - m);
                acc[kt][i][j] = p;
                s += p;
            }
        #pragma unroll
        for (int o = 8; o >= 1; o >>= 1)
            s += __shfl_xor_sync(0xffffffffu, s, o);
        rinv[i] = 1.0f / s;
    }

    const size_t abase = (size_t)(n * 12 + h) * 384 * 384;
    #pragma unroll
    for (int i = 0; i < 4; i++) {
        const int q = q0 + ty*4 + i;
        #pragma unroll
        for (int kt = 0; kt < 6; kt++) {
            float4 o = {acc[kt][i][0]*rinv[i], acc[kt][i][1]*rinv[i],
                        acc[kt][i][2]*rinv[i], acc[kt][i][3]*rinv[i]};
            *(float4*)(attn + abase + (size_t)q * 384 + kt*64 + tx*4) = o;
        }
    }
}

// ================= O[n,q,h*64+d] = sum_k attn[n,h,q,k] * v[n,k,h*64+d] =================
__global__ void __launch_bounds__(256) av_kernel(
    const float* __restrict__ attn, const float* __restrict__ v, float* __restrict__ oh)
{
    const int n = blockIdx.z, h = blockIdx.y, q0 = blockIdx.x * 64;
    const int tid = threadIdx.x;
    const int tx = tid & 15, ty = tid >> 4;
    __shared__ float Ps[16][68];   // Ps[kk][qi]
    __shared__ float Vs[16][68];   // Vs[kk][dj]
    float acc[4][4] = {};
    const float* Ab = attn + (size_t)(n * 12 + h) * 384 * 384;
    const float* Vb = v + (size_t)n * 384 * 768 + h * 64;

    const int lr = tid >> 2;          // q row for P load
    const int lk = (tid & 3) << 2;    // k offset for P load
    const int vr = tid >> 4;          // k row for V load (0..15)
    const int vc = (tid & 15) * 4;    // d col for V load

    for (int k0 = 0; k0 < 384; k0 += 16) {
        float4 p  = *(const float4*)(Ab + (size_t)(q0 + lr) * 384 + k0 + lk);
        float4 vv = *(const float4*)(Vb + (size_t)(k0 + vr) * 768 + vc);
        Ps[lk+0][lr]=p.x; Ps[lk+1][lr]=p.y; Ps[lk+2][lr]=p.z; Ps[lk+3][lr]=p.w;
        *(float4*)&Vs[vr][vc] = vv;
        __syncthreads();
        #pragma unroll
        for (int kk = 0; kk < 16; kk++) {
            float4 av = *(const float4*)&Ps[kk][ty*4];
            float4 bv = *(const float4*)&Vs[kk][tx*4];
            float qa[4] = {av.x, av.y, av.z, av.w};
            float kb[4] = {bv.x, bv.y, bv.z, bv.w};
            #pragma unroll
            for (int i = 0; i < 4; i++)
                #pragma unroll
                for (int j = 0; j < 4; j++)
                    acc[i][j] = fmaf(qa[i], kb[j], acc[i][j]);
        }
        __syncthreads();
    }
    #pragma unroll
    for (int i = 0; i < 4; i++) {
        float4 o = {acc[i][0], acc[i][1], acc[i][2], acc[i][3]};
        *(float4*)(oh + (size_t)(n * 384 + q0 + ty*4 + i) * 768 + h * 64 + tx*4) = o;
    }
}

// ================= host launcher =================
extern "C" void kernel_launch(void* const* d_in, const int* in_sizes, int n_in,
                              void* d_out, int out_size)
{
    const float* value = (const float*)d_in[0];
    const float* key   = (const float*)d_in[1];
    const float* query = (const float*)d_in[2];
    const int*   mask  = (const int*)  d_in[3];
    const float* Wq    = (const float*)d_in[4];
    const float* bq    = (const float*)d_in[5];
    const float* Wkc   = (const float*)d_in[6];
    const float* bkc   = (const float*)d_in[7];
    const float* Wkp   = (const float*)d_in[8];
    const float* bkp   = (const float*)d_in[9];
    const float* Wv    = (const float*)d_in[10];
    const float* bv    = (const float*)d_in[11];
    const float* Wfc   = (const float*)d_in[12];
    const float* bfc   = (const float*)d_in[13];
    const float* pos   = (const float*)d_in[14];

    float *qh, *kc, *v, *kpe, *z, *oh, *afb;
    cudaGetSymbolAddress((void**)&qh,  g_qh);
    cudaGetSymbolAddress((void**)&kc,  g_kc);
    cudaGetSymbolAddress((void**)&v,   g_v);
    cudaGetSymbolAddress((void**)&kpe, g_kpe);
    cudaGetSymbolAddress((void**)&z,   g_z);
    cudaGetSymbolAddress((void**)&oh,  g_oh);
    cudaGetSymbolAddress((void**)&afb, g_attn_fb);

    float* out  = (float*)d_out;
    const int OUT_ELEMS  = 8 * 384 * 768;        // 2359296
    const int ATTN_ELEMS = 8 * 12 * 384 * 384;   // 14155776
    float* attn = (out_size >= OUT_ELEMS + ATTN_ELEMS) ? (out + OUT_ELEMS) : afb;

    dim3 blk(256);
    // projections
    gemm_nt_bias_kernel<<<dim3(12, 48), blk>>>(query, Wq,  bq,  qh,  3072, 768, 768);
    gemm_nt_bias_kernel<<<dim3(12, 48), blk>>>(key,   Wkc, bkc, kc,  3072, 768, 768);
    gemm_nt_bias_kernel<<<dim3(12, 48), blk>>>(value, Wv,  bv,  v,   3072, 768, 768);
    // kpe = pos_emb @ Wkp^T + bkp   (the DeBERTa trick: replaces the 174-GFLOP pe GEMM)
    gemm_nt_bias_kernel<<<dim3(12, 12), blk>>>(pos,   Wkp, bkp, kpe, 768, 768, 768);
    // Z[n,h,q,c] = qh_h @ kpe_h^T
    zgemm_kernel<<<dim3(12, 6, 96), blk>>>(qh, kpe, z);
    // scores + mask + softmax -> attn
    scores_softmax_kernel<<<dim3(6, 12, 8), blk>>>(qh, kc, z, mask, attn);
    // O = attn @ V (written in [n,q,e] layout)
    av_kernel<<<dim3(6, 12, 8), blk>>>(attn, v, oh);
    // out = O @ Wfc^T + bfc
    gemm_nt_bias_kernel<<<dim3(12, 48), blk>>>(oh, Wfc, bfc, out, 3072, 768, 768);
}